// round 3
// baseline (speedup 1.0000x reference)
#include <cuda_runtime.h>
#include <cuda_bf16.h>
#include <cstddef>

// Problem constants
#define Bq  2
#define Sq  2048
#define Hq  2048
#define NHq 32
#define HDq 64

// Scratch: Q, K, V projections and attention output, all [B, S, H] row-major.
// (head h occupies columns h*64 .. h*64+63)
__device__ float g_Q[Bq * Sq * Hq];
__device__ float g_K[Bq * Sq * Hq];
__device__ float g_V[Bq * Sq * Hq];
__device__ float g_A[Bq * Sq * Hq];

// ---------------------------------------------------------------------------
// SGEMM (NT): C[m][n] = sum_k A[m][k] * W[n][k]
// A: [M,K] row-major, W: [N,K] row-major (weight), C: [M,N] row-major.
// Tiles: BM=BN=128, BK=8. 256 threads, 8x8 micro-tile per thread.
// Smem transposed with +4 pad: scalar transpose-stores are bank-conflict-free,
// compute reads are float4 (16B aligned since 132 % 4 == 0).
// ---------------------------------------------------------------------------
__global__ __launch_bounds__(256)
void sgemm_nt(const float* __restrict__ A, const float* __restrict__ W,
              float* __restrict__ C, int M, int N, int K) {
    __shared__ float As[8][132];
    __shared__ float Ws[8][132];

    const int tid = threadIdx.x;
    const int tx = tid & 15;
    const int ty = tid >> 4;
    const int m0 = blockIdx.y * 128;
    const int n0 = blockIdx.x * 128;

    // Loader mapping: 256 threads x 1 float4 each per operand per tile
    const int lrow = tid >> 1;        // 0..127
    const int lcol = (tid & 1) * 4;   // 0 or 4

    const float* Ag = A + (size_t)(m0 + lrow) * K + lcol;
    const float* Wg = W + (size_t)(n0 + lrow) * K + lcol;

    float acc[8][8];
#pragma unroll
    for (int i = 0; i < 8; ++i)
#pragma unroll
        for (int j = 0; j < 8; ++j) acc[i][j] = 0.0f;

    float4 pa = *(const float4*)Ag;
    float4 pw = *(const float4*)Wg;

    const int NT = K >> 3;
    for (int t = 0; t < NT; ++t) {
        // store prefetched tile (transposed)
        As[lcol + 0][lrow] = pa.x; As[lcol + 1][lrow] = pa.y;
        As[lcol + 2][lrow] = pa.z; As[lcol + 3][lrow] = pa.w;
        Ws[lcol + 0][lrow] = pw.x; Ws[lcol + 1][lrow] = pw.y;
        Ws[lcol + 2][lrow] = pw.z; Ws[lcol + 3][lrow] = pw.w;
        __syncthreads();

        if (t + 1 < NT) {
            pa = *(const float4*)(Ag + (size_t)(t + 1) * 8);
            pw = *(const float4*)(Wg + (size_t)(t + 1) * 8);
        }

#pragma unroll
        for (int k = 0; k < 8; ++k) {
            float4 a0 = *(const float4*)&As[k][ty * 8];
            float4 a1 = *(const float4*)&As[k][ty * 8 + 4];
            float4 w0 = *(const float4*)&Ws[k][tx * 8];
            float4 w1 = *(const float4*)&Ws[k][tx * 8 + 4];
            float av[8] = {a0.x, a0.y, a0.z, a0.w, a1.x, a1.y, a1.z, a1.w};
            float wv[8] = {w0.x, w0.y, w0.z, w0.w, w1.x, w1.y, w1.z, w1.w};
#pragma unroll
            for (int i = 0; i < 8; ++i)
#pragma unroll
                for (int j = 0; j < 8; ++j)
                    acc[i][j] += av[i] * wv[j];
        }
        __syncthreads();
    }

#pragma unroll
    for (int i = 0; i < 8; ++i) {
        float* Cr = C + (size_t)(m0 + ty * 8 + i) * N + n0 + tx * 8;
        *(float4*)(Cr + 0) = make_float4(acc[i][0], acc[i][1], acc[i][2], acc[i][3]);
        *(float4*)(Cr + 4) = make_float4(acc[i][4], acc[i][5], acc[i][6], acc[i][7]);
    }
}

// ---------------------------------------------------------------------------
// RoPE (in-place) on Q and K. Q additionally folded with 1/sqrt(HD) = 0.125.
// One thread handles one (d, d+32) rotation pair.
// ---------------------------------------------------------------------------
__global__ void rope_kernel(float* __restrict__ Q, float* __restrict__ K,
                            const float* __restrict__ cs,
                            const float* __restrict__ sn) {
    const int PAIRS = Bq * Sq * NHq * (HDq / 2);  // 4,194,304
    int idx = blockIdx.x * blockDim.x + threadIdx.x;
    if (idx >= 2 * PAIRS) return;
    bool isQ = idx < PAIRS;
    int p = isQ ? idx : idx - PAIRS;

    int d = p & 31;
    int h = (p >> 5) & 31;
    int s = (p >> 10) & 2047;
    int b = p >> 21;

    size_t base = ((size_t)(b * Sq + s) * Hq) + (size_t)h * HDq + d;
    float c1 = cs[s * HDq + d],      s1 = sn[s * HDq + d];
    float c2 = cs[s * HDq + d + 32], s2 = sn[s * HDq + d + 32];

    float* T = isQ ? Q : K;
    float scale = isQ ? 0.125f : 1.0f;
    float x1 = T[base];
    float x2 = T[base + 32];
    T[base]      = (x1 * c1 - x2 * s1) * scale;
    T[base + 32] = (x2 * c2 + x1 * s2) * scale;
}

// ---------------------------------------------------------------------------
// Flash attention (fp32), one CTA per (b, h, 64-row q tile).
// Smem: Qs (Q transposed, swizzled), KP (K transposed swizzled, then reused
// for P row-major), Vs (V row-major). Exactly 48 KB static.
// Thread layout: 16x16, each thread owns a 4x4 micro-tile of S and of O.
// ---------------------------------------------------------------------------
__global__ __launch_bounds__(256)
void attn_kernel(const float* __restrict__ Q, const float* __restrict__ K,
                 const float* __restrict__ V, const float* __restrict__ mask,
                 float* __restrict__ O) {
    __shared__ float Qs[4096];  // Qs[d][r], float4-group swizzled on (d & 15)
    __shared__ float KP[4096];  // K: KP[d][c] swizzled; later P: KP[r][c]
    __shared__ float Vs[4096];  // Vs[c][d] row-major

    const int tid = threadIdx.x;
    const int tx = tid & 15;
    const int ty = tid >> 4;
    const int b  = blockIdx.z;
    const int h  = blockIdx.y;
    const int q0 = blockIdx.x * 64;
    const size_t headoff = (size_t)h * HDq;

    const float* Qb = Q + ((size_t)(b * Sq + q0) * Hq) + headoff;

    // Load Q tile transposed + swizzled: element (row r, dim d) ->
    // Qs[d*64 + (((r>>2) ^ (d&15))<<2 | (r&3))]
#pragma unroll
    for (int it = 0; it < 4; ++it) {
        int f = tid + it * 256;
        int r = f >> 4;               // 0..63
        int d0 = (f & 15) << 2;       // 0..60
        float4 v = *(const float4*)(Qb + (size_t)r * Hq + d0);
        float vv[4] = {v.x, v.y, v.z, v.w};
#pragma unroll
        for (int u = 0; u < 4; ++u) {
            int d = d0 + u;
            Qs[d * 64 + ((((r >> 2) ^ (d & 15)) << 2) | (r & 3))] = vv[u];
        }
    }

    float o[4][4];
#pragma unroll
    for (int i = 0; i < 4; ++i)
#pragma unroll
        for (int j = 0; j < 4; ++j) o[i][j] = 0.0f;
    float mrow[4] = {-1e30f, -1e30f, -1e30f, -1e30f};
    float lrow[4] = {0.f, 0.f, 0.f, 0.f};

    __syncthreads();

    for (int t = 0; t < Sq / 64; ++t) {
        const int c0 = t * 64;
        const float* Kb = K + ((size_t)(b * Sq + c0) * Hq) + headoff;
        const float* Vb = V + ((size_t)(b * Sq + c0) * Hq) + headoff;

        // Load K (transposed+swizzled) and V (row-major)
#pragma unroll
        for (int it = 0; it < 4; ++it) {
            int f = tid + it * 256;
            int r = f >> 4;
            int d0 = (f & 15) << 2;
            float4 kv = *(const float4*)(Kb + (size_t)r * Hq + d0);
            float kvv[4] = {kv.x, kv.y, kv.z, kv.w};
#pragma unroll
            for (int u = 0; u < 4; ++u) {
                int d = d0 + u;
                KP[d * 64 + ((((r >> 2) ^ (d & 15)) << 2) | (r & 3))] = kvv[u];
            }
            float4 vv = *(const float4*)(Vb + (size_t)r * Hq + d0);
            *(float4*)&Vs[r * 64 + d0] = vv;
        }
        __syncthreads();

        // S = Qtile @ Ktile^T   (Q already scaled by 1/8)
        float s[4][4];
#pragma unroll
        for (int i = 0; i < 4; ++i)
#pragma unroll
            for (int j = 0; j < 4; ++j) s[i][j] = 0.0f;

#pragma unroll 8
        for (int d = 0; d < 64; ++d) {
            int sw = d & 15;
            float4 qa = *(const float4*)&Qs[d * 64 + ((ty ^ sw) << 2)];
            float4 kb = *(const float4*)&KP[d * 64 + ((tx ^ sw) << 2)];
            float qv[4] = {qa.x, qa.y, qa.z, qa.w};
            float kv2[4] = {kb.x, kb.y, kb.z, kb.w};
#pragma unroll
            for (int i = 0; i < 4; ++i)
#pragma unroll
                for (int j = 0; j < 4; ++j)
                    s[i][j] += qv[i] * kv2[j];
        }

        // additive attention mask (broadcast over query rows)
        float mk[4];
#pragma unroll
        for (int j = 0; j < 4; ++j)
            mk[j] = mask[(size_t)b * Sq + c0 + tx * 4 + j];
#pragma unroll
        for (int i = 0; i < 4; ++i)
#pragma unroll
            for (int j = 0; j < 4; ++j) s[i][j] += mk[j];

        // Online softmax update, per owned row
#pragma unroll
        for (int i = 0; i < 4; ++i) {
            float tm = fmaxf(fmaxf(s[i][0], s[i][1]), fmaxf(s[i][2], s[i][3]));
            tm = fmaxf(tm, __shfl_xor_sync(0xffffffffu, tm, 1));
            tm = fmaxf(tm, __shfl_xor_sync(0xffffffffu, tm, 2));
            tm = fmaxf(tm, __shfl_xor_sync(0xffffffffu, tm, 4));
            tm = fmaxf(tm, __shfl_xor_sync(0xffffffffu, tm, 8));
            float mnew = fmaxf(mrow[i], tm);
            float fac = __expf(mrow[i] - mnew);
            mrow[i] = mnew;
            float ssum = 0.0f;
#pragma unroll
            for (int j = 0; j < 4; ++j) {
                float p = __expf(s[i][j] - mnew);
                s[i][j] = p;
                ssum += p;
            }
            ssum += __shfl_xor_sync(0xffffffffu, ssum, 1);
            ssum += __shfl_xor_sync(0xffffffffu, ssum, 2);
            ssum += __shfl_xor_sync(0xffffffffu, ssum, 4);
            ssum += __shfl_xor_sync(0xffffffffu, ssum, 8);
            lrow[i] = lrow[i] * fac + ssum;
#pragma unroll
            for (int j = 0; j < 4; ++j) o[i][j] *= fac;
        }

        __syncthreads();  // everyone done reading K from KP

        // Write P row-major into KP
#pragma unroll
        for (int i = 0; i < 4; ++i)
            *(float4*)&KP[(ty * 4 + i) * 64 + tx * 4] =
                make_float4(s[i][0], s[i][1], s[i][2], s[i][3]);
        __syncthreads();

        // O += P @ Vtile
#pragma unroll 4
        for (int k = 0; k < 64; ++k) {
            float4 vv = *(const float4*)&Vs[k * 64 + (tx << 2)];
#pragma unroll
            for (int i = 0; i < 4; ++i) {
                float p = KP[(ty * 4 + i) * 64 + k];
                o[i][0] += p * vv.x;
                o[i][1] += p * vv.y;
                o[i][2] += p * vv.z;
                o[i][3] += p * vv.w;
            }
        }
        __syncthreads();  // before next tile's loads overwrite KP/Vs
    }

    // Epilogue: normalize and write
    float* Ob = O + ((size_t)(b * Sq + q0) * Hq) + headoff;
#pragma unroll
    for (int i = 0; i < 4; ++i) {
        float inv = 1.0f / lrow[i];
        *(float4*)(Ob + (size_t)(ty * 4 + i) * Hq + tx * 4) =
            make_float4(o[i][0] * inv, o[i][1] * inv, o[i][2] * inv, o[i][3] * inv);
    }
}

// ---------------------------------------------------------------------------
// Launch: QKV proj -> RoPE(+scale) -> flash attention -> output proj
// ---------------------------------------------------------------------------
extern "C" void kernel_launch(void* const* d_in, const int* in_sizes, int n_in,
                              void* d_out, int out_size) {
    const float* X    = (const float*)d_in[0];  // hidden_states [B,S,H]
    const float* mask = (const float*)d_in[1];  // attention_mask [B,S]
    const float* cs   = (const float*)d_in[2];  // cos [S,HD]
    const float* sn   = (const float*)d_in[3];  // sin [S,HD]
    const float* Wq   = (const float*)d_in[4];
    const float* Wk   = (const float*)d_in[5];
    const float* Wv   = (const float*)d_in[6];
    const float* Wo   = (const float*)d_in[7];
    float* out = (float*)d_out;

    float *Qp, *Kp, *Vp, *Ap;
    cudaGetSymbolAddress((void**)&Qp, g_Q);
    cudaGetSymbolAddress((void**)&Kp, g_K);
    cudaGetSymbolAddress((void**)&Vp, g_V);
    cudaGetSymbolAddress((void**)&Ap, g_A);

    const int M = Bq * Sq;                 // 4096
    dim3 gg(Hq / 128, M / 128);            // (16, 32)

    sgemm_nt<<<gg, 256>>>(X, Wq, Qp, M, Hq, Hq);
    sgemm_nt<<<gg, 256>>>(X, Wk, Kp, M, Hq, Hq);
    sgemm_nt<<<gg, 256>>>(X, Wv, Vp, M, Hq, Hq);

    const int PAIRS = Bq * Sq * NHq * (HDq / 2);
    rope_kernel<<<(2 * PAIRS + 255) / 256, 256>>>(Qp, Kp, cs, sn);

    attn_kernel<<<dim3(Sq / 64, NHq, Bq), 256>>>(Qp, Kp, Vp, mask, Ap);

    sgemm_nt<<<gg, 256>>>(Ap, Wo, out, M, Hq, Hq);
}

// round 4
// speedup vs baseline: 1.1954x; 1.1954x over previous
#include <cuda_runtime.h>
#include <cuda_bf16.h>
#include <cstddef>
#include <cstdint>

// Problem constants
#define Bq  2
#define Sq  2048
#define Hq  2048
#define NHq 32
#define HDq 64

// Scratch: Q, K, V projections and attention output, all [B, S, H] row-major.
__device__ float g_Q[Bq * Sq * Hq];
__device__ float g_K[Bq * Sq * Hq];
__device__ float g_V[Bq * Sq * Hq];
__device__ float g_A[Bq * Sq * Hq];

// ---------------------------------------------------------------------------
// TF32 helpers
// ---------------------------------------------------------------------------
__device__ __forceinline__ void tf32_split(float x, uint32_t& hi, uint32_t& lo) {
    asm("cvt.rna.tf32.f32 %0, %1;" : "=r"(hi) : "f"(x));
    float l = x - __uint_as_float(hi);
    asm("cvt.rna.tf32.f32 %0, %1;" : "=r"(lo) : "f"(l));
}

__device__ __forceinline__ void mma_tf32(float c[4], const uint32_t a[4],
                                         const uint32_t b[2]) {
    asm volatile(
        "mma.sync.aligned.m16n8k8.row.col.f32.tf32.tf32.f32 "
        "{%0,%1,%2,%3}, {%4,%5,%6,%7}, {%8,%9}, {%0,%1,%2,%3};\n"
        : "+f"(c[0]), "+f"(c[1]), "+f"(c[2]), "+f"(c[3])
        : "r"(a[0]), "r"(a[1]), "r"(a[2]), "r"(a[3]), "r"(b[0]), "r"(b[1]));
}

// ---------------------------------------------------------------------------
// Tensor-core GEMM (NT): C[m][n] = sum_k A[m][k] * W[n][k]
// 3xTF32 split for fp32-faithful accuracy.
// Block tile 128x128, K-chunk 32. 256 threads = 8 warps, warp tile 64x32,
// per warp 4 m-atoms x 4 n-atoms of m16n8k8.
// Smem: Ahi/Alo/Bhi/Blo stored transposed [k][mn], stride 136,
// XOR-swizzled col = mn ^ (k & 28)  -> conflict-free stores AND frag loads.
// Dynamic smem 69,632 B (1 CTA/SM).
// ---------------------------------------------------------------------------
__global__ __launch_bounds__(256, 1)
void sgemm_tf32_nt(const float* __restrict__ A, const float* __restrict__ W,
                   float* __restrict__ C, int M, int N, int K) {
    extern __shared__ uint32_t sm[];
    uint32_t* Ahi = sm;
    uint32_t* Alo = sm + 32 * 136;
    uint32_t* Bhi = sm + 2 * 32 * 136;
    uint32_t* Blo = sm + 3 * 32 * 136;

    const int tid  = threadIdx.x;
    const int lane = tid & 31;
    const int wid  = tid >> 5;
    const int wm   = (wid & 1) * 64;   // warp m offset in block tile
    const int wn   = (wid >> 1) * 32;  // warp n offset
    const int g    = lane >> 2;        // group id 0..7
    const int tig  = lane & 3;         // thread-in-group

    const int m0 = blockIdx.y * 128;
    const int n0 = blockIdx.x * 128;

    // Loader mapping: each thread loads 4 float4 per operand per chunk
    const int lm = tid >> 3;           // 0..31
    const int lk = (tid & 7) * 4;      // 0..28

    const float* Ag = A + (size_t)(m0 + lm) * K + lk;
    const float* Wg = W + (size_t)(n0 + lm) * K + lk;

    float acc[4][4][4];
#pragma unroll
    for (int i = 0; i < 4; ++i)
#pragma unroll
        for (int j = 0; j < 4; ++j)
#pragma unroll
            for (int r = 0; r < 4; ++r) acc[i][j][r] = 0.0f;

    float4 pa[4], pw[4];
#pragma unroll
    for (int it = 0; it < 4; ++it) {
        pa[it] = *(const float4*)(Ag + (size_t)it * 32 * K);
        pw[it] = *(const float4*)(Wg + (size_t)it * 32 * K);
    }

    const int NCH = K >> 5;  // chunks of 32
    for (int ch = 0; ch < NCH; ++ch) {
        // Split + transpose-store prefetched tiles into smem
#pragma unroll
        for (int it = 0; it < 4; ++it) {
            int m = lm + it * 32;
            float va[4] = {pa[it].x, pa[it].y, pa[it].z, pa[it].w};
            float vw[4] = {pw[it].x, pw[it].y, pw[it].z, pw[it].w};
#pragma unroll
            for (int u = 0; u < 4; ++u) {
                int k   = lk + u;
                int col = m ^ (k & 28);
                uint32_t h, l;
                tf32_split(va[u], h, l);
                Ahi[k * 136 + col] = h;
                Alo[k * 136 + col] = l;
                tf32_split(vw[u], h, l);
                Bhi[k * 136 + col] = h;
                Blo[k * 136 + col] = l;
            }
        }
        __syncthreads();

        if (ch + 1 < NCH) {
            const float* Ap = Ag + (size_t)(ch + 1) * 32;
            const float* Wp = Wg + (size_t)(ch + 1) * 32;
#pragma unroll
            for (int it = 0; it < 4; ++it) {
                pa[it] = *(const float4*)(Ap + (size_t)it * 32 * K);
                pw[it] = *(const float4*)(Wp + (size_t)it * 32 * K);
            }
        }

        // 4 k-steps of m16n8k8
#pragma unroll
        for (int ks = 0; ks < 4; ++ks) {
            const int ka  = ks * 8 + tig;      // k for a0/a1/b0
            const int kb  = ka + 4;            // k for a2/a3/b1
            const int swa = ka & 28;
            const int swb = kb & 28;

            uint32_t ah[4][4], al[4][4];
#pragma unroll
            for (int ma = 0; ma < 4; ++ma) {
                int r0 = wm + ma * 16 + g;
                int r1 = r0 + 8;
                ah[ma][0] = Ahi[ka * 136 + (r0 ^ swa)];
                ah[ma][1] = Ahi[ka * 136 + (r1 ^ swa)];
                ah[ma][2] = Ahi[kb * 136 + (r0 ^ swb)];
                ah[ma][3] = Ahi[kb * 136 + (r1 ^ swb)];
                al[ma][0] = Alo[ka * 136 + (r0 ^ swa)];
                al[ma][1] = Alo[ka * 136 + (r1 ^ swa)];
                al[ma][2] = Alo[kb * 136 + (r0 ^ swb)];
                al[ma][3] = Alo[kb * 136 + (r1 ^ swb)];
            }
            uint32_t bh[4][2], bl[4][2];
#pragma unroll
            for (int na = 0; na < 4; ++na) {
                int c = wn + na * 8 + g;
                bh[na][0] = Bhi[ka * 136 + (c ^ swa)];
                bh[na][1] = Bhi[kb * 136 + (c ^ swb)];
                bl[na][0] = Blo[ka * 136 + (c ^ swa)];
                bl[na][1] = Blo[kb * 136 + (c ^ swb)];
            }
#pragma unroll
            for (int ma = 0; ma < 4; ++ma)
#pragma unroll
                for (int na = 0; na < 4; ++na) {
                    mma_tf32(acc[ma][na], ah[ma], bh[na]);
                    mma_tf32(acc[ma][na], al[ma], bh[na]);
                    mma_tf32(acc[ma][na], ah[ma], bl[na]);
                }
        }
        __syncthreads();
    }

    // Epilogue: per-atom float2 stores
#pragma unroll
    for (int ma = 0; ma < 4; ++ma) {
        int r0 = m0 + wm + ma * 16 + g;
#pragma unroll
        for (int na = 0; na < 4; ++na) {
            int c = n0 + wn + na * 8 + 2 * tig;
            *(float2*)&C[(size_t)r0 * N + c] =
                make_float2(acc[ma][na][0], acc[ma][na][1]);
            *(float2*)&C[(size_t)(r0 + 8) * N + c] =
                make_float2(acc[ma][na][2], acc[ma][na][3]);
        }
    }
}

// ---------------------------------------------------------------------------
// RoPE (in-place) on Q and K. Q additionally folded with 1/sqrt(HD) = 0.125.
// ---------------------------------------------------------------------------
__global__ void rope_kernel(float* __restrict__ Q, float* __restrict__ K,
                            const float* __restrict__ cs,
                            const float* __restrict__ sn) {
    const int PAIRS = Bq * Sq * NHq * (HDq / 2);
    int idx = blockIdx.x * blockDim.x + threadIdx.x;
    if (idx >= 2 * PAIRS) return;
    bool isQ = idx < PAIRS;
    int p = isQ ? idx : idx - PAIRS;

    int d = p & 31;
    int h = (p >> 5) & 31;
    int s = (p >> 10) & 2047;
    int b = p >> 21;

    size_t base = ((size_t)(b * Sq + s) * Hq) + (size_t)h * HDq + d;
    float c1 = cs[s * HDq + d],      s1 = sn[s * HDq + d];
    float c2 = cs[s * HDq + d + 32], s2 = sn[s * HDq + d + 32];

    float* T = isQ ? Q : K;
    float scale = isQ ? 0.125f : 1.0f;
    float x1 = T[base];
    float x2 = T[base + 32];
    T[base]      = (x1 * c1 - x2 * s1) * scale;
    T[base + 32] = (x2 * c2 + x1 * s2) * scale;
}

// ---------------------------------------------------------------------------
// Flash attention (fp32), one CTA per (b, h, 64-row q tile). Unchanged.
// ---------------------------------------------------------------------------
__global__ __launch_bounds__(256)
void attn_kernel(const float* __restrict__ Q, const float* __restrict__ K,
                 const float* __restrict__ V, const float* __restrict__ mask,
                 float* __restrict__ O) {
    __shared__ float Qs[4096];  // Qs[d][r], float4-group swizzled on (d & 15)
    __shared__ float KP[4096];  // K: KP[d][c] swizzled; later P: KP[r][c]
    __shared__ float Vs[4096];  // Vs[c][d] row-major

    const int tid = threadIdx.x;
    const int tx = tid & 15;
    const int ty = tid >> 4;
    const int b  = blockIdx.z;
    const int h  = blockIdx.y;
    const int q0 = blockIdx.x * 64;
    const size_t headoff = (size_t)h * HDq;

    const float* Qb = Q + ((size_t)(b * Sq + q0) * Hq) + headoff;

#pragma unroll
    for (int it = 0; it < 4; ++it) {
        int f = tid + it * 256;
        int r = f >> 4;
        int d0 = (f & 15) << 2;
        float4 v = *(const float4*)(Qb + (size_t)r * Hq + d0);
        float vv[4] = {v.x, v.y, v.z, v.w};
#pragma unroll
        for (int u = 0; u < 4; ++u) {
            int d = d0 + u;
            Qs[d * 64 + ((((r >> 2) ^ (d & 15)) << 2) | (r & 3))] = vv[u];
        }
    }

    float o[4][4];
#pragma unroll
    for (int i = 0; i < 4; ++i)
#pragma unroll
        for (int j = 0; j < 4; ++j) o[i][j] = 0.0f;
    float mrow[4] = {-1e30f, -1e30f, -1e30f, -1e30f};
    float lrow[4] = {0.f, 0.f, 0.f, 0.f};

    __syncthreads();

    for (int t = 0; t < Sq / 64; ++t) {
        const int c0 = t * 64;
        const float* Kb = K + ((size_t)(b * Sq + c0) * Hq) + headoff;
        const float* Vb = V + ((size_t)(b * Sq + c0) * Hq) + headoff;

#pragma unroll
        for (int it = 0; it < 4; ++it) {
            int f = tid + it * 256;
            int r = f >> 4;
            int d0 = (f & 15) << 2;
            float4 kv = *(const float4*)(Kb + (size_t)r * Hq + d0);
            float kvv[4] = {kv.x, kv.y, kv.z, kv.w};
#pragma unroll
            for (int u = 0; u < 4; ++u) {
                int d = d0 + u;
                KP[d * 64 + ((((r >> 2) ^ (d & 15)) << 2) | (r & 3))] = kvv[u];
            }
            float4 vv = *(const float4*)(Vb + (size_t)r * Hq + d0);
            *(float4*)&Vs[r * 64 + d0] = vv;
        }
        __syncthreads();

        float s[4][4];
#pragma unroll
        for (int i = 0; i < 4; ++i)
#pragma unroll
            for (int j = 0; j < 4; ++j) s[i][j] = 0.0f;

#pragma unroll 8
        for (int d = 0; d < 64; ++d) {
            int sw = d & 15;
            float4 qa = *(const float4*)&Qs[d * 64 + ((ty ^ sw) << 2)];
            float4 kb = *(const float4*)&KP[d * 64 + ((tx ^ sw) << 2)];
            float qv[4] = {qa.x, qa.y, qa.z, qa.w};
            float kv2[4] = {kb.x, kb.y, kb.z, kb.w};
#pragma unroll
            for (int i = 0; i < 4; ++i)
#pragma unroll
                for (int j = 0; j < 4; ++j)
                    s[i][j] += qv[i] * kv2[j];
        }

        float mk[4];
#pragma unroll
        for (int j = 0; j < 4; ++j)
            mk[j] = mask[(size_t)b * Sq + c0 + tx * 4 + j];
#pragma unroll
        for (int i = 0; i < 4; ++i)
#pragma unroll
            for (int j = 0; j < 4; ++j) s[i][j] += mk[j];

#pragma unroll
        for (int i = 0; i < 4; ++i) {
            float tm = fmaxf(fmaxf(s[i][0], s[i][1]), fmaxf(s[i][2], s[i][3]));
            tm = fmaxf(tm, __shfl_xor_sync(0xffffffffu, tm, 1));
            tm = fmaxf(tm, __shfl_xor_sync(0xffffffffu, tm, 2));
            tm = fmaxf(tm, __shfl_xor_sync(0xffffffffu, tm, 4));
            tm = fmaxf(tm, __shfl_xor_sync(0xffffffffu, tm, 8));
            float mnew = fmaxf(mrow[i], tm);
            float fac = __expf(mrow[i] - mnew);
            mrow[i] = mnew;
            float ssum = 0.0f;
#pragma unroll
            for (int j = 0; j < 4; ++j) {
                float p = __expf(s[i][j] - mnew);
                s[i][j] = p;
                ssum += p;
            }
            ssum += __shfl_xor_sync(0xffffffffu, ssum, 1);
            ssum += __shfl_xor_sync(0xffffffffu, ssum, 2);
            ssum += __shfl_xor_sync(0xffffffffu, ssum, 4);
            ssum += __shfl_xor_sync(0xffffffffu, ssum, 8);
            lrow[i] = lrow[i] * fac + ssum;
#pragma unroll
            for (int j = 0; j < 4; ++j) o[i][j] *= fac;
        }

        __syncthreads();

#pragma unroll
        for (int i = 0; i < 4; ++i)
            *(float4*)&KP[(ty * 4 + i) * 64 + tx * 4] =
                make_float4(s[i][0], s[i][1], s[i][2], s[i][3]);
        __syncthreads();

#pragma unroll 4
        for (int k = 0; k < 64; ++k) {
            float4 vv = *(const float4*)&Vs[k * 64 + (tx << 2)];
#pragma unroll
            for (int i = 0; i < 4; ++i) {
                float p = KP[(ty * 4 + i) * 64 + k];
                o[i][0] += p * vv.x;
                o[i][1] += p * vv.y;
                o[i][2] += p * vv.z;
                o[i][3] += p * vv.w;
            }
        }
        __syncthreads();
    }

    float* Ob = O + ((size_t)(b * Sq + q0) * Hq) + headoff;
#pragma unroll
    for (int i = 0; i < 4; ++i) {
        float inv = 1.0f / lrow[i];
        *(float4*)(Ob + (size_t)(ty * 4 + i) * Hq + tx * 4) =
            make_float4(o[i][0] * inv, o[i][1] * inv, o[i][2] * inv, o[i][3] * inv);
    }
}

// ---------------------------------------------------------------------------
// Launch: QKV proj (tf32 TC) -> RoPE -> flash attention -> output proj
// ---------------------------------------------------------------------------
extern "C" void kernel_launch(void* const* d_in, const int* in_sizes, int n_in,
                              void* d_out, int out_size) {
    const float* X    = (const float*)d_in[0];
    const float* mask = (const float*)d_in[1];
    const float* cs   = (const float*)d_in[2];
    const float* sn   = (const float*)d_in[3];
    const float* Wq   = (const float*)d_in[4];
    const float* Wk   = (const float*)d_in[5];
    const float* Wv   = (const float*)d_in[6];
    const float* Wo   = (const float*)d_in[7];
    float* out = (float*)d_out;

    float *Qp, *Kp, *Vp, *Ap;
    cudaGetSymbolAddress((void**)&Qp, g_Q);
    cudaGetSymbolAddress((void**)&Kp, g_K);
    cudaGetSymbolAddress((void**)&Vp, g_V);
    cudaGetSymbolAddress((void**)&Ap, g_A);

    const int M = Bq * Sq;                 // 4096
    dim3 gg(Hq / 128, M / 128);            // (16, 32)

    const size_t shm = 4u * 32u * 136u * sizeof(uint32_t);  // 69,632 B
    static bool attr_set = false;
    if (!attr_set) {
        cudaFuncSetAttribute(sgemm_tf32_nt,
                             cudaFuncAttributeMaxDynamicSharedMemorySize,
                             (int)shm);
        attr_set = true;
    }

    sgemm_tf32_nt<<<gg, 256, shm>>>(X, Wq, Qp, M, Hq, Hq);
    sgemm_tf32_nt<<<gg, 256, shm>>>(X, Wk, Kp, M, Hq, Hq);
    sgemm_tf32_nt<<<gg, 256, shm>>>(X, Wv, Vp, M, Hq, Hq);

    const int PAIRS = Bq * Sq * NHq * (HDq / 2);
    rope_kernel<<<(2 * PAIRS + 255) / 256, 256>>>(Qp, Kp, cs, sn);

    attn_kernel<<<dim3(Sq / 64, NHq, Bq), 256>>>(Qp, Kp, Vp, mask, Ap);

    sgemm_tf32_nt<<<gg, 256, shm>>>(Ap, Wo, out, M, Hq, Hq);
}

// round 5
// speedup vs baseline: 1.5047x; 1.2588x over previous
#include <cuda_runtime.h>
#include <cuda_bf16.h>
#include <cstddef>
#include <cstdint>

// Problem constants
#define Bq  2
#define Sq  2048
#define Hq  2048
#define NHq 32
#define HDq 64

// Scratch buffers
__device__ float g_Q[Bq * Sq * Hq];
__device__ float g_K[Bq * Sq * Hq];
__device__ float g_V[Bq * Sq * Hq];
__device__ float g_A[Bq * Sq * Hq];

// ---------------------------------------------------------------------------
// TF32 helpers
// ---------------------------------------------------------------------------
__device__ __forceinline__ void tf32_split(float x, uint32_t& hi, uint32_t& lo) {
    asm("cvt.rna.tf32.f32 %0, %1;" : "=r"(hi) : "f"(x));
    float l = x - __uint_as_float(hi);
    asm("cvt.rna.tf32.f32 %0, %1;" : "=r"(lo) : "f"(l));
}

__device__ __forceinline__ void mma_tf32(float c[4], const uint32_t a[4],
                                         const uint32_t b[2]) {
    asm volatile(
        "mma.sync.aligned.m16n8k8.row.col.f32.tf32.tf32.f32 "
        "{%0,%1,%2,%3}, {%4,%5,%6,%7}, {%8,%9}, {%0,%1,%2,%3};\n"
        : "+f"(c[0]), "+f"(c[1]), "+f"(c[2]), "+f"(c[3])
        : "r"(a[0]), "r"(a[1]), "r"(a[2]), "r"(a[3]), "r"(b[0]), "r"(b[1]));
}

// ---------------------------------------------------------------------------
// GEMM core (NT): C[m][n] = sum_k A[m][k] * W[n][k], 3xTF32 split.
// Block tile 128x128, K-chunk 32, 256 threads, warp tile 64x32.
// ---------------------------------------------------------------------------
__device__ __forceinline__ void gemm_core(uint32_t* sm,
                                          const float* __restrict__ A,
                                          const float* __restrict__ W,
                                          float* __restrict__ C,
                                          int M, int N, int K,
                                          int m0, int n0) {
    uint32_t* Ahi = sm;
    uint32_t* Alo = sm + 32 * 136;
    uint32_t* Bhi = sm + 2 * 32 * 136;
    uint32_t* Blo = sm + 3 * 32 * 136;

    const int tid  = threadIdx.x;
    const int lane = tid & 31;
    const int wid  = tid >> 5;
    const int wm   = (wid & 1) * 64;
    const int wn   = (wid >> 1) * 32;
    const int g    = lane >> 2;
    const int tig  = lane & 3;

    const int lm = tid >> 3;
    const int lk = (tid & 7) * 4;

    const float* Ag = A + (size_t)(m0 + lm) * K + lk;
    const float* Wg = W + (size_t)(n0 + lm) * K + lk;

    float acc[4][4][4];
#pragma unroll
    for (int i = 0; i < 4; ++i)
#pragma unroll
        for (int j = 0; j < 4; ++j)
#pragma unroll
            for (int r = 0; r < 4; ++r) acc[i][j][r] = 0.0f;

    float4 pa[4], pw[4];
#pragma unroll
    for (int it = 0; it < 4; ++it) {
        pa[it] = *(const float4*)(Ag + (size_t)it * 32 * K);
        pw[it] = *(const float4*)(Wg + (size_t)it * 32 * K);
    }

    const int NCH = K >> 5;
    for (int ch = 0; ch < NCH; ++ch) {
#pragma unroll
        for (int it = 0; it < 4; ++it) {
            int m = lm + it * 32;
            float va[4] = {pa[it].x, pa[it].y, pa[it].z, pa[it].w};
            float vw[4] = {pw[it].x, pw[it].y, pw[it].z, pw[it].w};
#pragma unroll
            for (int u = 0; u < 4; ++u) {
                int k   = lk + u;
                int col = m ^ (k & 28);
                uint32_t h, l;
                tf32_split(va[u], h, l);
                Ahi[k * 136 + col] = h;
                Alo[k * 136 + col] = l;
                tf32_split(vw[u], h, l);
                Bhi[k * 136 + col] = h;
                Blo[k * 136 + col] = l;
            }
        }
        __syncthreads();

        if (ch + 1 < NCH) {
            const float* Ap = Ag + (size_t)(ch + 1) * 32;
            const float* Wp = Wg + (size_t)(ch + 1) * 32;
#pragma unroll
            for (int it = 0; it < 4; ++it) {
                pa[it] = *(const float4*)(Ap + (size_t)it * 32 * K);
                pw[it] = *(const float4*)(Wp + (size_t)it * 32 * K);
            }
        }

#pragma unroll
        for (int ks = 0; ks < 4; ++ks) {
            const int ka  = ks * 8 + tig;
            const int kb  = ka + 4;
            const int swa = ka & 28;
            const int swb = kb & 28;

            uint32_t ah[4][4], al[4][4];
#pragma unroll
            for (int ma = 0; ma < 4; ++ma) {
                int r0 = wm + ma * 16 + g;
                int r1 = r0 + 8;
                ah[ma][0] = Ahi[ka * 136 + (r0 ^ swa)];
                ah[ma][1] = Ahi[ka * 136 + (r1 ^ swa)];
                ah[ma][2] = Ahi[kb * 136 + (r0 ^ swb)];
                ah[ma][3] = Ahi[kb * 136 + (r1 ^ swb)];
                al[ma][0] = Alo[ka * 136 + (r0 ^ swa)];
                al[ma][1] = Alo[ka * 136 + (r1 ^ swa)];
                al[ma][2] = Alo[kb * 136 + (r0 ^ swb)];
                al[ma][3] = Alo[kb * 136 + (r1 ^ swb)];
            }
            uint32_t bh[4][2], bl[4][2];
#pragma unroll
            for (int na = 0; na < 4; ++na) {
                int c = wn + na * 8 + g;
                bh[na][0] = Bhi[ka * 136 + (c ^ swa)];
                bh[na][1] = Bhi[kb * 136 + (c ^ swb)];
                bl[na][0] = Blo[ka * 136 + (c ^ swa)];
                bl[na][1] = Blo[kb * 136 + (c ^ swb)];
            }
#pragma unroll
            for (int ma = 0; ma < 4; ++ma)
#pragma unroll
                for (int na = 0; na < 4; ++na) {
                    mma_tf32(acc[ma][na], ah[ma], bh[na]);
                    mma_tf32(acc[ma][na], al[ma], bh[na]);
                    mma_tf32(acc[ma][na], ah[ma], bl[na]);
                }
        }
        __syncthreads();
    }

#pragma unroll
    for (int ma = 0; ma < 4; ++ma) {
        int r0 = m0 + wm + ma * 16 + g;
#pragma unroll
        for (int na = 0; na < 4; ++na) {
            int c = n0 + wn + na * 8 + 2 * tig;
            *(float2*)&C[(size_t)r0 * N + c] =
                make_float2(acc[ma][na][0], acc[ma][na][1]);
            *(float2*)&C[(size_t)(r0 + 8) * N + c] =
                make_float2(acc[ma][na][2], acc[ma][na][3]);
        }
    }
}

__global__ __launch_bounds__(256, 1)
void sgemm_tf32_nt(const float* __restrict__ A, const float* __restrict__ W,
                   float* __restrict__ C, int M, int N, int K) {
    extern __shared__ uint32_t smg[];
    gemm_core(smg, A, W, C, M, N, K, blockIdx.y * 128, blockIdx.x * 128);
}

// Fused QKV: blockIdx.x in [0,48): selects Wq/Wk/Wv and output buffer.
__global__ __launch_bounds__(256, 1)
void sgemm_tf32_qkv(const float* __restrict__ X,
                    const float* __restrict__ Wqp, const float* __restrict__ Wkp,
                    const float* __restrict__ Wvp,
                    float* __restrict__ Qo, float* __restrict__ Ko,
                    float* __restrict__ Vo) {
    extern __shared__ uint32_t smg[];
    const int which = blockIdx.x >> 4;
    const float* W = (which == 0) ? Wqp : (which == 1) ? Wkp : Wvp;
    float* C = (which == 0) ? Qo : (which == 1) ? Ko : Vo;
    gemm_core(smg, X, W, C, Bq * Sq, Hq, Hq,
              blockIdx.y * 128, (blockIdx.x & 15) * 128);
}

// ---------------------------------------------------------------------------
// RoPE (in-place) on Q and K. Q also folded with 1/sqrt(HD) = 0.125.
// ---------------------------------------------------------------------------
__global__ void rope_kernel(float* __restrict__ Q, float* __restrict__ K,
                            const float* __restrict__ cs,
                            const float* __restrict__ sn) {
    const int PAIRS = Bq * Sq * NHq * (HDq / 2);
    int idx = blockIdx.x * blockDim.x + threadIdx.x;
    if (idx >= 2 * PAIRS) return;
    bool isQ = idx < PAIRS;
    int p = isQ ? idx : idx - PAIRS;

    int d = p & 31;
    int h = (p >> 5) & 31;
    int s = (p >> 10) & 2047;
    int b = p >> 21;

    size_t base = ((size_t)(b * Sq + s) * Hq) + (size_t)h * HDq + d;
    float c1 = cs[s * HDq + d],      s1 = sn[s * HDq + d];
    float c2 = cs[s * HDq + d + 32], s2 = sn[s * HDq + d + 32];

    float* T = isQ ? Q : K;
    float scale = isQ ? 0.125f : 1.0f;
    float x1 = T[base];
    float x2 = T[base + 32];
    T[base]      = (x1 * c1 - x2 * s1) * scale;
    T[base + 32] = (x2 * c2 + x1 * s2) * scale;
}

// ---------------------------------------------------------------------------
// Flash attention on tensor cores (tf32 3-mma split).
// CTA: 128 q-rows, 256 threads = 8 warps; each warp owns 16 q-rows x full
// 64-col KV tile (rows warp-private -> softmax reduces within thread quads,
// P@V reads only the warp's own P rows; 2 CTA syncs per tile).
// Smem (dynamic, 98,560 B; 2 CTAs/SM):
//   Qs[128][64]  fp32, swizzle d ^= (r&7)<<2
//   Ks[ 64][64]  fp32, swizzle d ^= (kv&7)<<2
//   Vs[ 64][64]  fp32, swizzle d ^= (kv&7)<<3
//   Ps[128][64]  fp32, swizzle kv ^= (r&7)<<2
//   msk[64]
// All mma fragment LDS are provably bank-conflict-free per instruction.
// ---------------------------------------------------------------------------
__global__ __launch_bounds__(256, 2)
void attn_mma(const float* __restrict__ Q, const float* __restrict__ K,
              const float* __restrict__ V, const float* __restrict__ mask,
              float* __restrict__ O) {
    extern __shared__ float sma[];
    float* Qs  = sma;            // 8192
    float* Ks  = sma + 8192;     // 4096
    float* Vs  = sma + 12288;    // 4096
    float* Ps  = sma + 16384;    // 8192
    float* msk = sma + 24576;    // 64

    const int tid  = threadIdx.x;
    const int lane = tid & 31;
    const int wid  = tid >> 5;
    const int g    = lane >> 2;
    const int tig  = lane & 3;
    const int rb   = wid * 16;
    const int R    = rb + g;       // R&7 == g
    const int R8   = R + 8;        // R8&7 == g
    const int sw   = g << 2;

    const int b  = blockIdx.z;
    const int h  = blockIdx.y;
    const int q0 = blockIdx.x * 128;
    const size_t ho = (size_t)h * HDq;

    const float* Qb = Q + ((size_t)(b * Sq + q0) * Hq) + ho;
#pragma unroll
    for (int it = 0; it < 8; ++it) {
        int f = tid + it * 256;
        int r = f >> 4, d0 = (f & 15) << 2;
        float4 v = *(const float4*)(Qb + (size_t)r * Hq + d0);
        *(float4*)&Qs[r * 64 + (d0 ^ ((r & 7) << 2))] = v;
    }

    float o[8][4];
#pragma unroll
    for (int na = 0; na < 8; ++na)
#pragma unroll
        for (int e = 0; e < 4; ++e) o[na][e] = 0.0f;
    float mrow[2] = {-1e30f, -1e30f};
    float lrow[2] = {0.0f, 0.0f};

    for (int t = 0; t < Sq / 64; ++t) {
        const int c0 = t * 64;
        const float* Kb = K + ((size_t)(b * Sq + c0) * Hq) + ho;
        const float* Vb = V + ((size_t)(b * Sq + c0) * Hq) + ho;
#pragma unroll
        for (int it = 0; it < 4; ++it) {
            int f = tid + it * 256;
            int r = f >> 4, d0 = (f & 15) << 2;
            *(float4*)&Ks[r * 64 + (d0 ^ ((r & 7) << 2))] =
                *(const float4*)(Kb + (size_t)r * Hq + d0);
            *(float4*)&Vs[r * 64 + (d0 ^ ((r & 7) << 3))] =
                *(const float4*)(Vb + (size_t)r * Hq + d0);
        }
        if (tid < 16)
            *(float4*)&msk[tid * 4] =
                *(const float4*)(mask + (size_t)b * Sq + c0 + tid * 4);
        __syncthreads();

        // ---- S = Q @ K^T (tf32 3-mma) ----
        float s[8][4];
#pragma unroll
        for (int na = 0; na < 8; ++na)
#pragma unroll
            for (int e = 0; e < 4; ++e) s[na][e] = 0.0f;

#pragma unroll
        for (int ks = 0; ks < 8; ++ks) {
            const int ka = ks * 8 + tig;
            const int kb = ka + 4;
            float q0v = Qs[R * 64 + (ka ^ sw)];
            float q1v = Qs[R8 * 64 + (ka ^ sw)];
            float q2v = Qs[R * 64 + (kb ^ sw)];
            float q3v = Qs[R8 * 64 + (kb ^ sw)];
            uint32_t ah[4], al[4];
            tf32_split(q0v, ah[0], al[0]);
            tf32_split(q1v, ah[1], al[1]);
            tf32_split(q2v, ah[2], al[2]);
            tf32_split(q3v, ah[3], al[3]);
#pragma unroll
            for (int na = 0; na < 8; ++na) {
                int c = na * 8 + g;
                float k0 = Ks[c * 64 + (ka ^ sw)];
                float k1 = Ks[c * 64 + (kb ^ sw)];
                uint32_t bh[2], bl[2];
                tf32_split(k0, bh[0], bl[0]);
                tf32_split(k1, bh[1], bl[1]);
                mma_tf32(s[na], ah, bh);
                mma_tf32(s[na], al, bh);
                mma_tf32(s[na], ah, bl);
            }
        }

        // ---- mask + online softmax ----
#pragma unroll
        for (int na = 0; na < 8; ++na) {
            float m0 = msk[na * 8 + 2 * tig];
            float m1 = msk[na * 8 + 2 * tig + 1];
            s[na][0] += m0; s[na][1] += m1;
            s[na][2] += m0; s[na][3] += m1;
        }

        float mx0 = -1e30f, mx1 = -1e30f;
#pragma unroll
        for (int na = 0; na < 8; ++na) {
            mx0 = fmaxf(mx0, fmaxf(s[na][0], s[na][1]));
            mx1 = fmaxf(mx1, fmaxf(s[na][2], s[na][3]));
        }
        mx0 = fmaxf(mx0, __shfl_xor_sync(0xffffffffu, mx0, 1));
        mx0 = fmaxf(mx0, __shfl_xor_sync(0xffffffffu, mx0, 2));
        mx1 = fmaxf(mx1, __shfl_xor_sync(0xffffffffu, mx1, 1));
        mx1 = fmaxf(mx1, __shfl_xor_sync(0xffffffffu, mx1, 2));

        float mn0 = fmaxf(mrow[0], mx0);
        float mn1 = fmaxf(mrow[1], mx1);
        float fac0 = __expf(mrow[0] - mn0);
        float fac1 = __expf(mrow[1] - mn1);
        mrow[0] = mn0; mrow[1] = mn1;

        float sum0 = 0.0f, sum1 = 0.0f;
#pragma unroll
        for (int na = 0; na < 8; ++na) {
            s[na][0] = __expf(s[na][0] - mn0); sum0 += s[na][0];
            s[na][1] = __expf(s[na][1] - mn0); sum0 += s[na][1];
            s[na][2] = __expf(s[na][2] - mn1); sum1 += s[na][2];
            s[na][3] = __expf(s[na][3] - mn1); sum1 += s[na][3];
        }
        sum0 += __shfl_xor_sync(0xffffffffu, sum0, 1);
        sum0 += __shfl_xor_sync(0xffffffffu, sum0, 2);
        sum1 += __shfl_xor_sync(0xffffffffu, sum1, 1);
        sum1 += __shfl_xor_sync(0xffffffffu, sum1, 2);
        lrow[0] = lrow[0] * fac0 + sum0;
        lrow[1] = lrow[1] * fac1 + sum1;

#pragma unroll
        for (int na = 0; na < 8; ++na) {
            o[na][0] *= fac0; o[na][1] *= fac0;
            o[na][2] *= fac1; o[na][3] *= fac1;
        }

        // ---- store P (warp-private rows) ----
#pragma unroll
        for (int na = 0; na < 8; ++na) {
            int col = na * 8 + 2 * tig;
            *(float2*)&Ps[R * 64 + (col ^ sw)] = make_float2(s[na][0], s[na][1]);
            *(float2*)&Ps[R8 * 64 + (col ^ sw)] = make_float2(s[na][2], s[na][3]);
        }
        __syncwarp();

        // ---- O += P @ V (tf32 3-mma) ----
#pragma unroll
        for (int ks = 0; ks < 8; ++ks) {
            const int kva = ks * 8 + tig;
            const int kvb = kva + 4;
            float p0 = Ps[R * 64 + (kva ^ sw)];
            float p1 = Ps[R8 * 64 + (kva ^ sw)];
            float p2 = Ps[R * 64 + (kvb ^ sw)];
            float p3 = Ps[R8 * 64 + (kvb ^ sw)];
            uint32_t ph[4], pl[4];
            tf32_split(p0, ph[0], pl[0]);
            tf32_split(p1, ph[1], pl[1]);
            tf32_split(p2, ph[2], pl[2]);
            tf32_split(p3, ph[3], pl[3]);
            const int swa = tig << 3;
            const int swb = (tig + 4) << 3;
#pragma unroll
            for (int na = 0; na < 8; ++na) {
                int c = na * 8 + g;
                float v0 = Vs[kva * 64 + (c ^ swa)];
                float v1 = Vs[kvb * 64 + (c ^ swb)];
                uint32_t vh[2], vl[2];
                tf32_split(v0, vh[0], vl[0]);
                tf32_split(v1, vh[1], vl[1]);
                mma_tf32(o[na], ph, vh);
                mma_tf32(o[na], pl, vh);
                mma_tf32(o[na], ph, vl);
            }
        }
        __syncthreads();
    }

    // Epilogue
    float i0 = 1.0f / lrow[0];
    float i1 = 1.0f / lrow[1];
    float* Ob = O + ((size_t)(b * Sq + q0) * Hq) + ho;
#pragma unroll
    for (int na = 0; na < 8; ++na) {
        int col = na * 8 + 2 * tig;
        *(float2*)&Ob[(size_t)R * Hq + col] =
            make_float2(o[na][0] * i0, o[na][1] * i0);
        *(float2*)&Ob[(size_t)R8 * Hq + col] =
            make_float2(o[na][2] * i1, o[na][3] * i1);
    }
}

// ---------------------------------------------------------------------------
// Launch
// ---------------------------------------------------------------------------
extern "C" void kernel_launch(void* const* d_in, const int* in_sizes, int n_in,
                              void* d_out, int out_size) {
    const float* X    = (const float*)d_in[0];
    const float* mask = (const float*)d_in[1];
    const float* cs   = (const float*)d_in[2];
    const float* sn   = (const float*)d_in[3];
    const float* Wq   = (const float*)d_in[4];
    const float* Wk   = (const float*)d_in[5];
    const float* Wv   = (const float*)d_in[6];
    const float* Wo   = (const float*)d_in[7];
    float* out = (float*)d_out;

    float *Qp, *Kp, *Vp, *Ap;
    cudaGetSymbolAddress((void**)&Qp, g_Q);
    cudaGetSymbolAddress((void**)&Kp, g_K);
    cudaGetSymbolAddress((void**)&Vp, g_V);
    cudaGetSymbolAddress((void**)&Ap, g_A);

    const int M = Bq * Sq;                               // 4096
    const size_t shm_g = 4u * 32u * 136u * sizeof(uint32_t);  // 69,632
    const size_t shm_a = 24640u * sizeof(float);              // 98,560

    static bool attr_set = false;
    if (!attr_set) {
        cudaFuncSetAttribute(sgemm_tf32_nt,
                             cudaFuncAttributeMaxDynamicSharedMemorySize,
                             (int)shm_g);
        cudaFuncSetAttribute(sgemm_tf32_qkv,
                             cudaFuncAttributeMaxDynamicSharedMemorySize,
                             (int)shm_g);
        cudaFuncSetAttribute(attn_mma,
                             cudaFuncAttributeMaxDynamicSharedMemorySize,
                             (int)shm_a);
        attr_set = true;
    }

    // Fused QKV projection: grid.x = 3 * 16 tiles
    sgemm_tf32_qkv<<<dim3(48, M / 128), 256, shm_g>>>(X, Wq, Wk, Wv,
                                                      Qp, Kp, Vp);

    const int PAIRS = Bq * Sq * NHq * (HDq / 2);
    rope_kernel<<<(2 * PAIRS + 255) / 256, 256>>>(Qp, Kp, cs, sn);

    attn_mma<<<dim3(Sq / 128, NHq, Bq), 256, shm_a>>>(Qp, Kp, Vp, mask, Ap);

    sgemm_tf32_nt<<<dim3(Hq / 128, M / 128), 256, shm_g>>>(Ap, Wo, out,
                                                           M, Hq, Hq);
}

// round 6
// speedup vs baseline: 1.7916x; 1.1906x over previous
#include <cuda_runtime.h>
#include <cuda_bf16.h>
#include <cstddef>
#include <cstdint>

// Problem constants
#define Bq  2
#define Sq  2048
#define Hq  2048
#define NHq 32
#define HDq 64

// Scratch buffers
__device__ float g_Q[Bq * Sq * Hq];
__device__ float g_K[Bq * Sq * Hq];
__device__ float g_V[Bq * Sq * Hq];
__device__ float g_A[Bq * Sq * Hq];

// ---------------------------------------------------------------------------
// TF32 helpers
// ---------------------------------------------------------------------------
__device__ __forceinline__ void tf32_split(float x, uint32_t& hi, uint32_t& lo) {
    asm("cvt.rna.tf32.f32 %0, %1;" : "=r"(hi) : "f"(x));
    float l = x - __uint_as_float(hi);
    asm("cvt.rna.tf32.f32 %0, %1;" : "=r"(lo) : "f"(l));
}

__device__ __forceinline__ uint32_t tf32_rna(float x) {
    uint32_t r;
    asm("cvt.rna.tf32.f32 %0, %1;" : "=r"(r) : "f"(x));
    return r;
}

__device__ __forceinline__ void mma_tf32(float c[4], const uint32_t a[4],
                                         const uint32_t b[2]) {
    asm volatile(
        "mma.sync.aligned.m16n8k8.row.col.f32.tf32.tf32.f32 "
        "{%0,%1,%2,%3}, {%4,%5,%6,%7}, {%8,%9}, {%0,%1,%2,%3};\n"
        : "+f"(c[0]), "+f"(c[1]), "+f"(c[2]), "+f"(c[3])
        : "r"(a[0]), "r"(a[1]), "r"(a[2]), "r"(a[3]), "r"(b[0]), "r"(b[1]));
}

// ---------------------------------------------------------------------------
// GEMM core (NT): C[m][n] = sum_k A[m][k] * W[n][k], 3xTF32 split.
// Block tile 128x128, K-chunk 32, 256 threads, warp tile 64x32.
// Two-stage smem double buffering: mma on stage (ch&1) overlaps the
// split+store of stage ((ch+1)&1); one __syncthreads per chunk.
// ---------------------------------------------------------------------------
#define GSSTR (4 * 32 * 136)   // uint32s per stage (69,632 B)

__device__ __forceinline__ void gemm_store_stage(uint32_t* stage,
                                                 const float4* pa,
                                                 const float4* pw,
                                                 int lm, int lk) {
    uint32_t* Ahi = stage;
    uint32_t* Alo = stage + 32 * 136;
    uint32_t* Bhi = stage + 2 * 32 * 136;
    uint32_t* Blo = stage + 3 * 32 * 136;
#pragma unroll
    for (int it = 0; it < 4; ++it) {
        int m = lm + it * 32;
        float va[4] = {pa[it].x, pa[it].y, pa[it].z, pa[it].w};
        float vw[4] = {pw[it].x, pw[it].y, pw[it].z, pw[it].w};
#pragma unroll
        for (int u = 0; u < 4; ++u) {
            int k   = lk + u;
            int col = m ^ (k & 28);
            uint32_t h, l;
            tf32_split(va[u], h, l);
            Ahi[k * 136 + col] = h;
            Alo[k * 136 + col] = l;
            tf32_split(vw[u], h, l);
            Bhi[k * 136 + col] = h;
            Blo[k * 136 + col] = l;
        }
    }
}

__device__ __forceinline__ void gemm_core(uint32_t* sm,
                                          const float* __restrict__ A,
                                          const float* __restrict__ W,
                                          float* __restrict__ C,
                                          int M, int N, int K,
                                          int m0, int n0) {
    const int tid  = threadIdx.x;
    const int lane = tid & 31;
    const int wid  = tid >> 5;
    const int wm   = (wid & 1) * 64;
    const int wn   = (wid >> 1) * 32;
    const int g    = lane >> 2;
    const int tig  = lane & 3;

    const int lm = tid >> 3;
    const int lk = (tid & 7) * 4;

    const float* Ag = A + (size_t)(m0 + lm) * K + lk;
    const float* Wg = W + (size_t)(n0 + lm) * K + lk;

    float acc[4][4][4];
#pragma unroll
    for (int i = 0; i < 4; ++i)
#pragma unroll
        for (int j = 0; j < 4; ++j)
#pragma unroll
            for (int r = 0; r < 4; ++r) acc[i][j][r] = 0.0f;

    float4 pa[4], pw[4];
#pragma unroll
    for (int it = 0; it < 4; ++it) {
        pa[it] = *(const float4*)(Ag + (size_t)it * 32 * K);
        pw[it] = *(const float4*)(Wg + (size_t)it * 32 * K);
    }
    gemm_store_stage(sm, pa, pw, lm, lk);
    __syncthreads();

    const int NCH = K >> 5;
    for (int ch = 0; ch < NCH; ++ch) {
        const bool more = (ch + 1 < NCH);
        if (more) {
            const float* Ap = Ag + (size_t)(ch + 1) * 32;
            const float* Wp = Wg + (size_t)(ch + 1) * 32;
#pragma unroll
            for (int it = 0; it < 4; ++it) {
                pa[it] = *(const float4*)(Ap + (size_t)it * 32 * K);
                pw[it] = *(const float4*)(Wp + (size_t)it * 32 * K);
            }
        }

        uint32_t* stage = sm + (ch & 1) * GSSTR;
        uint32_t* Ahi = stage;
        uint32_t* Alo = stage + 32 * 136;
        uint32_t* Bhi = stage + 2 * 32 * 136;
        uint32_t* Blo = stage + 3 * 32 * 136;

#pragma unroll
        for (int ks = 0; ks < 4; ++ks) {
            const int ka  = ks * 8 + tig;
            const int kb  = ka + 4;
            const int swa = ka & 28;
            const int swb = kb & 28;

            uint32_t ah[4][4], al[4][4];
#pragma unroll
            for (int ma = 0; ma < 4; ++ma) {
                int r0 = wm + ma * 16 + g;
                int r1 = r0 + 8;
                ah[ma][0] = Ahi[ka * 136 + (r0 ^ swa)];
                ah[ma][1] = Ahi[ka * 136 + (r1 ^ swa)];
                ah[ma][2] = Ahi[kb * 136 + (r0 ^ swb)];
                ah[ma][3] = Ahi[kb * 136 + (r1 ^ swb)];
                al[ma][0] = Alo[ka * 136 + (r0 ^ swa)];
                al[ma][1] = Alo[ka * 136 + (r1 ^ swa)];
                al[ma][2] = Alo[kb * 136 + (r0 ^ swb)];
                al[ma][3] = Alo[kb * 136 + (r1 ^ swb)];
            }
            uint32_t bh[4][2], bl[4][2];
#pragma unroll
            for (int na = 0; na < 4; ++na) {
                int c = wn + na * 8 + g;
                bh[na][0] = Bhi[ka * 136 + (c ^ swa)];
                bh[na][1] = Bhi[kb * 136 + (c ^ swb)];
                bl[na][0] = Blo[ka * 136 + (c ^ swa)];
                bl[na][1] = Blo[kb * 136 + (c ^ swb)];
            }
#pragma unroll
            for (int ma = 0; ma < 4; ++ma)
#pragma unroll
                for (int na = 0; na < 4; ++na) {
                    mma_tf32(acc[ma][na], ah[ma], bh[na]);
                    mma_tf32(acc[ma][na], al[ma], bh[na]);
                    mma_tf32(acc[ma][na], ah[ma], bl[na]);
                }
        }

        if (more)
            gemm_store_stage(sm + ((ch + 1) & 1) * GSSTR, pa, pw, lm, lk);
        __syncthreads();
    }

#pragma unroll
    for (int ma = 0; ma < 4; ++ma) {
        int r0 = m0 + wm + ma * 16 + g;
#pragma unroll
        for (int na = 0; na < 4; ++na) {
            int c = n0 + wn + na * 8 + 2 * tig;
            *(float2*)&C[(size_t)r0 * N + c] =
                make_float2(acc[ma][na][0], acc[ma][na][1]);
            *(float2*)&C[(size_t)(r0 + 8) * N + c] =
                make_float2(acc[ma][na][2], acc[ma][na][3]);
        }
    }
}

__global__ __launch_bounds__(256, 1)
void sgemm_tf32_nt(const float* __restrict__ A, const float* __restrict__ W,
                   float* __restrict__ C, int M, int N, int K) {
    extern __shared__ uint32_t smg[];
    gemm_core(smg, A, W, C, M, N, K, blockIdx.y * 128, blockIdx.x * 128);
}

// Fused QKV: blockIdx.x in [0,48): selects Wq/Wk/Wv and output buffer.
__global__ __launch_bounds__(256, 1)
void sgemm_tf32_qkv(const float* __restrict__ X,
                    const float* __restrict__ Wqp, const float* __restrict__ Wkp,
                    const float* __restrict__ Wvp,
                    float* __restrict__ Qo, float* __restrict__ Ko,
                    float* __restrict__ Vo) {
    extern __shared__ uint32_t smg[];
    const int which = blockIdx.x >> 4;
    const float* W = (which == 0) ? Wqp : (which == 1) ? Wkp : Wvp;
    float* C = (which == 0) ? Qo : (which == 1) ? Ko : Vo;
    gemm_core(smg, X, W, C, Bq * Sq, Hq, Hq,
              blockIdx.y * 128, (blockIdx.x & 15) * 128);
}

// ---------------------------------------------------------------------------
// RoPE (in-place) on Q and K. Q also folded with 1/sqrt(HD) = 0.125.
// ---------------------------------------------------------------------------
__global__ void rope_kernel(float* __restrict__ Q, float* __restrict__ K,
                            const float* __restrict__ cs,
                            const float* __restrict__ sn) {
    const int PAIRS = Bq * Sq * NHq * (HDq / 2);
    int idx = blockIdx.x * blockDim.x + threadIdx.x;
    if (idx >= 2 * PAIRS) return;
    bool isQ = idx < PAIRS;
    int p = isQ ? idx : idx - PAIRS;

    int d = p & 31;
    int h = (p >> 5) & 31;
    int s = (p >> 10) & 2047;
    int b = p >> 21;

    size_t base = ((size_t)(b * Sq + s) * Hq) + (size_t)h * HDq + d;
    float c1 = cs[s * HDq + d],      s1 = sn[s * HDq + d];
    float c2 = cs[s * HDq + d + 32], s2 = sn[s * HDq + d + 32];

    float* T = isQ ? Q : K;
    float scale = isQ ? 0.125f : 1.0f;
    float x1 = T[base];
    float x2 = T[base + 32];
    T[base]      = (x1 * c1 - x2 * s1) * scale;
    T[base + 32] = (x2 * c2 + x1 * s2) * scale;
}

// ---------------------------------------------------------------------------
// Flash attention on tensor cores, 2-mma tf32 split (a-operand corrected,
// b-operand single tf32). K and V are rounded to tf32 ONCE at smem-store
// time (cooperative), removing all per-warp redundant cvt work.
// CTA: 128 q-rows, 256 threads = 8 warps, each warp 16 rows x 64 kv cols.
// Smem 98,560 B -> 2 CTAs/SM.
// ---------------------------------------------------------------------------
__global__ __launch_bounds__(256, 2)
void attn_mma(const float* __restrict__ Q, const float* __restrict__ K,
              const float* __restrict__ V, const float* __restrict__ mask,
              float* __restrict__ O) {
    extern __shared__ uint32_t sma[];
    float*    Qs  = (float*)sma;          // 8192 floats
    uint32_t* Ks  = sma + 8192;           // 4096 (tf32 bits)
    uint32_t* Vs  = sma + 12288;          // 4096 (tf32 bits)
    float*    Ps  = (float*)(sma + 16384);// 8192 floats
    float*    msk = (float*)(sma + 24576);// 64

    const int tid  = threadIdx.x;
    const int lane = tid & 31;
    const int wid  = tid >> 5;
    const int g    = lane >> 2;
    const int tig  = lane & 3;
    const int R    = wid * 16 + g;
    const int R8   = R + 8;
    const int sw   = g << 2;

    const int b  = blockIdx.z;
    const int h  = blockIdx.y;
    const int q0 = blockIdx.x * 128;
    const size_t ho = (size_t)h * HDq;

    const float* Qb = Q + ((size_t)(b * Sq + q0) * Hq) + ho;
#pragma unroll
    for (int it = 0; it < 8; ++it) {
        int f = tid + it * 256;
        int r = f >> 4, d0 = (f & 15) << 2;
        float4 v = *(const float4*)(Qb + (size_t)r * Hq + d0);
        *(float4*)&Qs[r * 64 + (d0 ^ ((r & 7) << 2))] = v;
    }

    float o[8][4];
#pragma unroll
    for (int na = 0; na < 8; ++na)
#pragma unroll
        for (int e = 0; e < 4; ++e) o[na][e] = 0.0f;
    float mrow[2] = {-1e30f, -1e30f};
    float lrow[2] = {0.0f, 0.0f};

    for (int t = 0; t < Sq / 64; ++t) {
        const int c0 = t * 64;
        const float* Kb = K + ((size_t)(b * Sq + c0) * Hq) + ho;
        const float* Vb = V + ((size_t)(b * Sq + c0) * Hq) + ho;
#pragma unroll
        for (int it = 0; it < 4; ++it) {
            int f = tid + it * 256;
            int r = f >> 4, d0 = (f & 15) << 2;
            float4 kv = *(const float4*)(Kb + (size_t)r * Hq + d0);
            uint4 kq;
            kq.x = tf32_rna(kv.x); kq.y = tf32_rna(kv.y);
            kq.z = tf32_rna(kv.z); kq.w = tf32_rna(kv.w);
            *(uint4*)&Ks[r * 64 + (d0 ^ ((r & 7) << 2))] = kq;
            float4 vv = *(const float4*)(Vb + (size_t)r * Hq + d0);
            uint4 vq;
            vq.x = tf32_rna(vv.x); vq.y = tf32_rna(vv.y);
            vq.z = tf32_rna(vv.z); vq.w = tf32_rna(vv.w);
            *(uint4*)&Vs[r * 64 + (d0 ^ ((r & 7) << 3))] = vq;
        }
        if (tid < 16)
            *(float4*)&msk[tid * 4] =
                *(const float4*)(mask + (size_t)b * Sq + c0 + tid * 4);
        __syncthreads();

        // ---- S = Q @ K^T (2-mma: Q split, K tf32-rounded) ----
        float s[8][4];
#pragma unroll
        for (int na = 0; na < 8; ++na)
#pragma unroll
            for (int e = 0; e < 4; ++e) s[na][e] = 0.0f;

#pragma unroll
        for (int ks = 0; ks < 8; ++ks) {
            const int ka = ks * 8 + tig;
            const int kb2 = ka + 4;
            uint32_t ah[4], al[4];
            tf32_split(Qs[R * 64 + (ka ^ sw)],  ah[0], al[0]);
            tf32_split(Qs[R8 * 64 + (ka ^ sw)], ah[1], al[1]);
            tf32_split(Qs[R * 64 + (kb2 ^ sw)], ah[2], al[2]);
            tf32_split(Qs[R8 * 64 + (kb2 ^ sw)], ah[3], al[3]);
#pragma unroll
            for (int na = 0; na < 8; ++na) {
                int c = na * 8 + g;
                uint32_t bh[2];
                bh[0] = Ks[c * 64 + (ka ^ sw)];
                bh[1] = Ks[c * 64 + (kb2 ^ sw)];
                mma_tf32(s[na], ah, bh);
                mma_tf32(s[na], al, bh);
            }
        }

        // ---- mask + online softmax ----
#pragma unroll
        for (int na = 0; na < 8; ++na) {
            float m0 = msk[na * 8 + 2 * tig];
            float m1 = msk[na * 8 + 2 * tig + 1];
            s[na][0] += m0; s[na][1] += m1;
            s[na][2] += m0; s[na][3] += m1;
        }

        float mx0 = -1e30f, mx1 = -1e30f;
#pragma unroll
        for (int na = 0; na < 8; ++na) {
            mx0 = fmaxf(mx0, fmaxf(s[na][0], s[na][1]));
            mx1 = fmaxf(mx1, fmaxf(s[na][2], s[na][3]));
        }
        mx0 = fmaxf(mx0, __shfl_xor_sync(0xffffffffu, mx0, 1));
        mx0 = fmaxf(mx0, __shfl_xor_sync(0xffffffffu, mx0, 2));
        mx1 = fmaxf(mx1, __shfl_xor_sync(0xffffffffu, mx1, 1));
        mx1 = fmaxf(mx1, __shfl_xor_sync(0xffffffffu, mx1, 2));

        float mn0 = fmaxf(mrow[0], mx0);
        float mn1 = fmaxf(mrow[1], mx1);
        float fac0 = __expf(mrow[0] - mn0);
        float fac1 = __expf(mrow[1] - mn1);
        mrow[0] = mn0; mrow[1] = mn1;

        float sum0 = 0.0f, sum1 = 0.0f;
#pragma unroll
        for (int na = 0; na < 8; ++na) {
            s[na][0] = __expf(s[na][0] - mn0); sum0 += s[na][0];
            s[na][1] = __expf(s[na][1] - mn0); sum0 += s[na][1];
            s[na][2] = __expf(s[na][2] - mn1); sum1 += s[na][2];
            s[na][3] = __expf(s[na][3] - mn1); sum1 += s[na][3];
        }
        sum0 += __shfl_xor_sync(0xffffffffu, sum0, 1);
        sum0 += __shfl_xor_sync(0xffffffffu, sum0, 2);
        sum1 += __shfl_xor_sync(0xffffffffu, sum1, 1);
        sum1 += __shfl_xor_sync(0xffffffffu, sum1, 2);
        lrow[0] = lrow[0] * fac0 + sum0;
        lrow[1] = lrow[1] * fac1 + sum1;

#pragma unroll
        for (int na = 0; na < 8; ++na) {
            o[na][0] *= fac0; o[na][1] *= fac0;
            o[na][2] *= fac1; o[na][3] *= fac1;
        }

        // ---- store P (warp-private rows) ----
#pragma unroll
        for (int na = 0; na < 8; ++na) {
            int col = na * 8 + 2 * tig;
            *(float2*)&Ps[R * 64 + (col ^ sw)] = make_float2(s[na][0], s[na][1]);
            *(float2*)&Ps[R8 * 64 + (col ^ sw)] = make_float2(s[na][2], s[na][3]);
        }
        __syncwarp();

        // ---- O += P @ V (2-mma: P split, V tf32-rounded) ----
#pragma unroll
        for (int ks = 0; ks < 8; ++ks) {
            const int kva = ks * 8 + tig;
            const int kvb = kva + 4;
            uint32_t ph[4], pl[4];
            tf32_split(Ps[R * 64 + (kva ^ sw)],  ph[0], pl[0]);
            tf32_split(Ps[R8 * 64 + (kva ^ sw)], ph[1], pl[1]);
            tf32_split(Ps[R * 64 + (kvb ^ sw)],  ph[2], pl[2]);
            tf32_split(Ps[R8 * 64 + (kvb ^ sw)], ph[3], pl[3]);
            const int swa = tig << 3;
            const int swb = (tig + 4) << 3;
#pragma unroll
            for (int na = 0; na < 8; ++na) {
                int c = na * 8 + g;
                uint32_t vh[2];
                vh[0] = Vs[kva * 64 + (c ^ swa)];
                vh[1] = Vs[kvb * 64 + (c ^ swb)];
                mma_tf32(o[na], ph, vh);
                mma_tf32(o[na], pl, vh);
            }
        }
        __syncthreads();
    }

    // Epilogue
    float i0 = 1.0f / lrow[0];
    float i1 = 1.0f / lrow[1];
    float* Ob = O + ((size_t)(b * Sq + q0) * Hq) + ho;
#pragma unroll
    for (int na = 0; na < 8; ++na) {
        int col = na * 8 + 2 * tig;
        *(float2*)&Ob[(size_t)R * Hq + col] =
            make_float2(o[na][0] * i0, o[na][1] * i0);
        *(float2*)&Ob[(size_t)R8 * Hq + col] =
            make_float2(o[na][2] * i1, o[na][3] * i1);
    }
}

// ---------------------------------------------------------------------------
// Launch
// ---------------------------------------------------------------------------
extern "C" void kernel_launch(void* const* d_in, const int* in_sizes, int n_in,
                              void* d_out, int out_size) {
    const float* X    = (const float*)d_in[0];
    const float* mask = (const float*)d_in[1];
    const float* cs   = (const float*)d_in[2];
    const float* sn   = (const float*)d_in[3];
    const float* Wq   = (const float*)d_in[4];
    const float* Wk   = (const float*)d_in[5];
    const float* Wv   = (const float*)d_in[6];
    const float* Wo   = (const float*)d_in[7];
    float* out = (float*)d_out;

    float *Qp, *Kp, *Vp, *Ap;
    cudaGetSymbolAddress((void**)&Qp, g_Q);
    cudaGetSymbolAddress((void**)&Kp, g_K);
    cudaGetSymbolAddress((void**)&Vp, g_V);
    cudaGetSymbolAddress((void**)&Ap, g_A);

    const int M = Bq * Sq;                                    // 4096
    const size_t shm_g = 2u * GSSTR * sizeof(uint32_t);       // 139,264
    const size_t shm_a = 24640u * sizeof(uint32_t);           // 98,560

    static bool attr_set = false;
    if (!attr_set) {
        cudaFuncSetAttribute(sgemm_tf32_nt,
                             cudaFuncAttributeMaxDynamicSharedMemorySize,
                             (int)shm_g);
        cudaFuncSetAttribute(sgemm_tf32_qkv,
                             cudaFuncAttributeMaxDynamicSharedMemorySize,
                             (int)shm_g);
        cudaFuncSetAttribute(attn_mma,
                             cudaFuncAttributeMaxDynamicSharedMemorySize,
                             (int)shm_a);
        attr_set = true;
    }

    sgemm_tf32_qkv<<<dim3(48, M / 128), 256, shm_g>>>(X, Wq, Wk, Wv,
                                                      Qp, Kp, Vp);

    const int PAIRS = Bq * Sq * NHq * (HDq / 2);
    rope_kernel<<<(2 * PAIRS + 255) / 256, 256>>>(Qp, Kp, cs, sn);

    attn_mma<<<dim3(Sq / 128, NHq, Bq), 256, shm_a>>>(Qp, Kp, Vp, mask, Ap);

    sgemm_tf32_nt<<<dim3(Hq / 128, M / 128), 256, shm_g>>>(Ap, Wo, out,
                                                           M, Hq, Hq);
}

// round 7
// speedup vs baseline: 2.2172x; 1.2375x over previous
#include <cuda_runtime.h>
#include <cuda_bf16.h>
#include <cstddef>
#include <cstdint>

// Problem constants
#define Bq  2
#define Sq  2048
#define Hq  2048
#define NHq 32
#define HDq 64

// Scratch buffers
__device__ float g_Q[Bq * Sq * Hq];
__device__ float g_K[Bq * Sq * Hq];
__device__ float g_V[Bq * Sq * Hq];
__device__ float g_A[Bq * Sq * Hq];

// ---------------------------------------------------------------------------
// TF32 helpers
// ---------------------------------------------------------------------------
__device__ __forceinline__ void tf32_split(float x, uint32_t& hi, uint32_t& lo) {
    asm("cvt.rna.tf32.f32 %0, %1;" : "=r"(hi) : "f"(x));
    float l = x - __uint_as_float(hi);
    asm("cvt.rna.tf32.f32 %0, %1;" : "=r"(lo) : "f"(l));
}

__device__ __forceinline__ uint32_t tf32_rna(float x) {
    uint32_t r;
    asm("cvt.rna.tf32.f32 %0, %1;" : "=r"(r) : "f"(x));
    return r;
}

__device__ __forceinline__ void mma_tf32(float c[4], const uint32_t a[4],
                                         const uint32_t b[2]) {
    asm volatile(
        "mma.sync.aligned.m16n8k8.row.col.f32.tf32.tf32.f32 "
        "{%0,%1,%2,%3}, {%4,%5,%6,%7}, {%8,%9}, {%0,%1,%2,%3};\n"
        : "+f"(c[0]), "+f"(c[1]), "+f"(c[2]), "+f"(c[3])
        : "r"(a[0]), "r"(a[1]), "r"(a[2]), "r"(a[3]), "r"(b[0]), "r"(b[1]));
}

// ---------------------------------------------------------------------------
// GEMM core (NT): C[m][n] = sum_k A[m][k] * W[n][k].
// 2-mma tf32: A (activations) split hi/lo; W rounded to a single tf32 at
// smem-store time. Block tile 128x128, K-chunk 32, 256 threads,
// warp tile 64x32. Single-stage smem (52,224 B), XOR swizzle
// col = mn ^ (k & 28) -> conflict-free stores and fragment loads.
// ---------------------------------------------------------------------------
#define GSSTR (3 * 32 * 136)   // uint32s total (52,224 B)

__device__ __forceinline__ void gemm_core(uint32_t* sm,
                                          const float* __restrict__ A,
                                          const float* __restrict__ W,
                                          float* __restrict__ C,
                                          int M, int N, int K,
                                          int m0, int n0) {
    uint32_t* Ahi = sm;
    uint32_t* Alo = sm + 32 * 136;
    uint32_t* Bh  = sm + 2 * 32 * 136;

    const int tid  = threadIdx.x;
    const int lane = tid & 31;
    const int wid  = tid >> 5;
    const int wm   = (wid & 1) * 64;
    const int wn   = (wid >> 1) * 32;
    const int g    = lane >> 2;
    const int tig  = lane & 3;

    const int lm = tid >> 3;
    const int lk = (tid & 7) * 4;

    const float* Ag = A + (size_t)(m0 + lm) * K + lk;
    const float* Wg = W + (size_t)(n0 + lm) * K + lk;

    float acc[4][4][4];
#pragma unroll
    for (int i = 0; i < 4; ++i)
#pragma unroll
        for (int j = 0; j < 4; ++j)
#pragma unroll
            for (int r = 0; r < 4; ++r) acc[i][j][r] = 0.0f;

    float4 pa[4], pw[4];
#pragma unroll
    for (int it = 0; it < 4; ++it) {
        pa[it] = *(const float4*)(Ag + (size_t)it * 32 * K);
        pw[it] = *(const float4*)(Wg + (size_t)it * 32 * K);
    }

    const int NCH = K >> 5;
    for (int ch = 0; ch < NCH; ++ch) {
        // split/round + transpose-store prefetched tiles
#pragma unroll
        for (int it = 0; it < 4; ++it) {
            int m = lm + it * 32;
            float va[4] = {pa[it].x, pa[it].y, pa[it].z, pa[it].w};
            float vw[4] = {pw[it].x, pw[it].y, pw[it].z, pw[it].w};
#pragma unroll
            for (int u = 0; u < 4; ++u) {
                int k   = lk + u;
                int col = m ^ (k & 28);
                uint32_t h, l;
                tf32_split(va[u], h, l);
                Ahi[k * 136 + col] = h;
                Alo[k * 136 + col] = l;
                Bh[k * 136 + col]  = tf32_rna(vw[u]);
            }
        }
        __syncthreads();

        if (ch + 1 < NCH) {
            const float* Ap = Ag + (size_t)(ch + 1) * 32;
            const float* Wp = Wg + (size_t)(ch + 1) * 32;
#pragma unroll
            for (int it = 0; it < 4; ++it) {
                pa[it] = *(const float4*)(Ap + (size_t)it * 32 * K);
                pw[it] = *(const float4*)(Wp + (size_t)it * 32 * K);
            }
        }

#pragma unroll
        for (int ks = 0; ks < 4; ++ks) {
            const int ka  = ks * 8 + tig;
            const int kb  = ka + 4;
            const int swa = ka & 28;
            const int swb = kb & 28;

            uint32_t ah[4][4], al[4][4];
#pragma unroll
            for (int ma = 0; ma < 4; ++ma) {
                int r0 = wm + ma * 16 + g;
                int r1 = r0 + 8;
                ah[ma][0] = Ahi[ka * 136 + (r0 ^ swa)];
                ah[ma][1] = Ahi[ka * 136 + (r1 ^ swa)];
                ah[ma][2] = Ahi[kb * 136 + (r0 ^ swb)];
                ah[ma][3] = Ahi[kb * 136 + (r1 ^ swb)];
                al[ma][0] = Alo[ka * 136 + (r0 ^ swa)];
                al[ma][1] = Alo[ka * 136 + (r1 ^ swa)];
                al[ma][2] = Alo[kb * 136 + (r0 ^ swb)];
                al[ma][3] = Alo[kb * 136 + (r1 ^ swb)];
            }
            uint32_t bh[4][2];
#pragma unroll
            for (int na = 0; na < 4; ++na) {
                int c = wn + na * 8 + g;
                bh[na][0] = Bh[ka * 136 + (c ^ swa)];
                bh[na][1] = Bh[kb * 136 + (c ^ swb)];
            }
#pragma unroll
            for (int ma = 0; ma < 4; ++ma)
#pragma unroll
                for (int na = 0; na < 4; ++na) {
                    mma_tf32(acc[ma][na], ah[ma], bh[na]);
                    mma_tf32(acc[ma][na], al[ma], bh[na]);
                }
        }
        __syncthreads();
    }

#pragma unroll
    for (int ma = 0; ma < 4; ++ma) {
        int r0 = m0 + wm + ma * 16 + g;
#pragma unroll
        for (int na = 0; na < 4; ++na) {
            int c = n0 + wn + na * 8 + 2 * tig;
            *(float2*)&C[(size_t)r0 * N + c] =
                make_float2(acc[ma][na][0], acc[ma][na][1]);
            *(float2*)&C[(size_t)(r0 + 8) * N + c] =
                make_float2(acc[ma][na][2], acc[ma][na][3]);
        }
    }
}

__global__ __launch_bounds__(256, 1)
void sgemm_tf32_nt(const float* __restrict__ A, const float* __restrict__ W,
                   float* __restrict__ C, int M, int N, int K) {
    extern __shared__ uint32_t smg[];
    gemm_core(smg, A, W, C, M, N, K, blockIdx.y * 128, blockIdx.x * 128);
}

// Fused QKV: blockIdx.x in [0,48): selects Wq/Wk/Wv and output buffer.
__global__ __launch_bounds__(256, 1)
void sgemm_tf32_qkv(const float* __restrict__ X,
                    const float* __restrict__ Wqp, const float* __restrict__ Wkp,
                    const float* __restrict__ Wvp,
                    float* __restrict__ Qo, float* __restrict__ Ko,
                    float* __restrict__ Vo) {
    extern __shared__ uint32_t smg[];
    const int which = blockIdx.x >> 4;
    const float* W = (which == 0) ? Wqp : (which == 1) ? Wkp : Wvp;
    float* C = (which == 0) ? Qo : (which == 1) ? Ko : Vo;
    gemm_core(smg, X, W, C, Bq * Sq, Hq, Hq,
              blockIdx.y * 128, (blockIdx.x & 15) * 128);
}

// ---------------------------------------------------------------------------
// RoPE (in-place) on Q and K. Q also folded with 1/sqrt(HD) = 0.125.
// ---------------------------------------------------------------------------
__global__ void rope_kernel(float* __restrict__ Q, float* __restrict__ K,
                            const float* __restrict__ cs,
                            const float* __restrict__ sn) {
    const int PAIRS = Bq * Sq * NHq * (HDq / 2);
    int idx = blockIdx.x * blockDim.x + threadIdx.x;
    if (idx >= 2 * PAIRS) return;
    bool isQ = idx < PAIRS;
    int p = isQ ? idx : idx - PAIRS;

    int d = p & 31;
    int h = (p >> 5) & 31;
    int s = (p >> 10) & 2047;
    int b = p >> 21;

    size_t base = ((size_t)(b * Sq + s) * Hq) + (size_t)h * HDq + d;
    float c1 = cs[s * HDq + d],      s1 = sn[s * HDq + d];
    float c2 = cs[s * HDq + d + 32], s2 = sn[s * HDq + d + 32];

    float* T = isQ ? Q : K;
    float scale = isQ ? 0.125f : 1.0f;
    float x1 = T[base];
    float x2 = T[base + 32];
    T[base]      = (x1 * c1 - x2 * s1) * scale;
    T[base + 32] = (x2 * c2 + x1 * s2) * scale;
}

// ---------------------------------------------------------------------------
// Flash attention on tensor cores, 2-mma tf32 split (unchanged from R6).
// ---------------------------------------------------------------------------
__global__ __launch_bounds__(256, 2)
void attn_mma(const float* __restrict__ Q, const float* __restrict__ K,
              const float* __restrict__ V, const float* __restrict__ mask,
              float* __restrict__ O) {
    extern __shared__ uint32_t sma[];
    float*    Qs  = (float*)sma;          // 8192 floats
    uint32_t* Ks  = sma + 8192;           // 4096 (tf32 bits)
    uint32_t* Vs  = sma + 12288;          // 4096 (tf32 bits)
    float*    Ps  = (float*)(sma + 16384);// 8192 floats
    float*    msk = (float*)(sma + 24576);// 64

    const int tid  = threadIdx.x;
    const int lane = tid & 31;
    const int wid  = tid >> 5;
    const int g    = lane >> 2;
    const int tig  = lane & 3;
    const int R    = wid * 16 + g;
    const int R8   = R + 8;
    const int sw   = g << 2;

    const int b  = blockIdx.z;
    const int h  = blockIdx.y;
    const int q0 = blockIdx.x * 128;
    const size_t ho = (size_t)h * HDq;

    const float* Qb = Q + ((size_t)(b * Sq + q0) * Hq) + ho;
#pragma unroll
    for (int it = 0; it < 8; ++it) {
        int f = tid + it * 256;
        int r = f >> 4, d0 = (f & 15) << 2;
        float4 v = *(const float4*)(Qb + (size_t)r * Hq + d0);
        *(float4*)&Qs[r * 64 + (d0 ^ ((r & 7) << 2))] = v;
    }

    float o[8][4];
#pragma unroll
    for (int na = 0; na < 8; ++na)
#pragma unroll
        for (int e = 0; e < 4; ++e) o[na][e] = 0.0f;
    float mrow[2] = {-1e30f, -1e30f};
    float lrow[2] = {0.0f, 0.0f};

    for (int t = 0; t < Sq / 64; ++t) {
        const int c0 = t * 64;
        const float* Kb = K + ((size_t)(b * Sq + c0) * Hq) + ho;
        const float* Vb = V + ((size_t)(b * Sq + c0) * Hq) + ho;
#pragma unroll
        for (int it = 0; it < 4; ++it) {
            int f = tid + it * 256;
            int r = f >> 4, d0 = (f & 15) << 2;
            float4 kv = *(const float4*)(Kb + (size_t)r * Hq + d0);
            uint4 kq;
            kq.x = tf32_rna(kv.x); kq.y = tf32_rna(kv.y);
            kq.z = tf32_rna(kv.z); kq.w = tf32_rna(kv.w);
            *(uint4*)&Ks[r * 64 + (d0 ^ ((r & 7) << 2))] = kq;
            float4 vv = *(const float4*)(Vb + (size_t)r * Hq + d0);
            uint4 vq;
            vq.x = tf32_rna(vv.x); vq.y = tf32_rna(vv.y);
            vq.z = tf32_rna(vv.z); vq.w = tf32_rna(vv.w);
            *(uint4*)&Vs[r * 64 + (d0 ^ ((r & 7) << 3))] = vq;
        }
        if (tid < 16)
            *(float4*)&msk[tid * 4] =
                *(const float4*)(mask + (size_t)b * Sq + c0 + tid * 4);
        __syncthreads();

        // ---- S = Q @ K^T ----
        float s[8][4];
#pragma unroll
        for (int na = 0; na < 8; ++na)
#pragma unroll
            for (int e = 0; e < 4; ++e) s[na][e] = 0.0f;

#pragma unroll
        for (int ks = 0; ks < 8; ++ks) {
            const int ka = ks * 8 + tig;
            const int kb2 = ka + 4;
            uint32_t ah[4], al[4];
            tf32_split(Qs[R * 64 + (ka ^ sw)],  ah[0], al[0]);
            tf32_split(Qs[R8 * 64 + (ka ^ sw)], ah[1], al[1]);
            tf32_split(Qs[R * 64 + (kb2 ^ sw)], ah[2], al[2]);
            tf32_split(Qs[R8 * 64 + (kb2 ^ sw)], ah[3], al[3]);
#pragma unroll
            for (int na = 0; na < 8; ++na) {
                int c = na * 8 + g;
                uint32_t bh[2];
                bh[0] = Ks[c * 64 + (ka ^ sw)];
                bh[1] = Ks[c * 64 + (kb2 ^ sw)];
                mma_tf32(s[na], ah, bh);
                mma_tf32(s[na], al, bh);
            }
        }

        // ---- mask + online softmax ----
#pragma unroll
        for (int na = 0; na < 8; ++na) {
            float m0 = msk[na * 8 + 2 * tig];
            float m1 = msk[na * 8 + 2 * tig + 1];
            s[na][0] += m0; s[na][1] += m1;
            s[na][2] += m0; s[na][3] += m1;
        }

        float mx0 = -1e30f, mx1 = -1e30f;
#pragma unroll
        for (int na = 0; na < 8; ++na) {
            mx0 = fmaxf(mx0, fmaxf(s[na][0], s[na][1]));
            mx1 = fmaxf(mx1, fmaxf(s[na][2], s[na][3]));
        }
        mx0 = fmaxf(mx0, __shfl_xor_sync(0xffffffffu, mx0, 1));
        mx0 = fmaxf(mx0, __shfl_xor_sync(0xffffffffu, mx0, 2));
        mx1 = fmaxf(mx1, __shfl_xor_sync(0xffffffffu, mx1, 1));
        mx1 = fmaxf(mx1, __shfl_xor_sync(0xffffffffu, mx1, 2));

        float mn0 = fmaxf(mrow[0], mx0);
        float mn1 = fmaxf(mrow[1], mx1);
        float fac0 = __expf(mrow[0] - mn0);
        float fac1 = __expf(mrow[1] - mn1);
        mrow[0] = mn0; mrow[1] = mn1;

        float sum0 = 0.0f, sum1 = 0.0f;
#pragma unroll
        for (int na = 0; na < 8; ++na) {
            s[na][0] = __expf(s[na][0] - mn0); sum0 += s[na][0];
            s[na][1] = __expf(s[na][1] - mn0); sum0 += s[na][1];
            s[na][2] = __expf(s[na][2] - mn1); sum1 += s[na][2];
            s[na][3] = __expf(s[na][3] - mn1); sum1 += s[na][3];
        }
        sum0 += __shfl_xor_sync(0xffffffffu, sum0, 1);
        sum0 += __shfl_xor_sync(0xffffffffu, sum0, 2);
        sum1 += __shfl_xor_sync(0xffffffffu, sum1, 1);
        sum1 += __shfl_xor_sync(0xffffffffu, sum1, 2);
        lrow[0] = lrow[0] * fac0 + sum0;
        lrow[1] = lrow[1] * fac1 + sum1;

#pragma unroll
        for (int na = 0; na < 8; ++na) {
            o[na][0] *= fac0; o[na][1] *= fac0;
            o[na][2] *= fac1; o[na][3] *= fac1;
        }

        // ---- store P (warp-private rows) ----
#pragma unroll
        for (int na = 0; na < 8; ++na) {
            int col = na * 8 + 2 * tig;
            *(float2*)&Ps[R * 64 + (col ^ sw)] = make_float2(s[na][0], s[na][1]);
            *(float2*)&Ps[R8 * 64 + (col ^ sw)] = make_float2(s[na][2], s[na][3]);
        }
        __syncwarp();

        // ---- O += P @ V ----
#pragma unroll
        for (int ks = 0; ks < 8; ++ks) {
            const int kva = ks * 8 + tig;
            const int kvb = kva + 4;
            uint32_t ph[4], pl[4];
            tf32_split(Ps[R * 64 + (kva ^ sw)],  ph[0], pl[0]);
            tf32_split(Ps[R8 * 64 + (kva ^ sw)], ph[1], pl[1]);
            tf32_split(Ps[R * 64 + (kvb ^ sw)],  ph[2], pl[2]);
            tf32_split(Ps[R8 * 64 + (kvb ^ sw)], ph[3], pl[3]);
            const int swa = tig << 3;
            const int swb = (tig + 4) << 3;
#pragma unroll
            for (int na = 0; na < 8; ++na) {
                int c = na * 8 + g;
                uint32_t vh[2];
                vh[0] = Vs[kva * 64 + (c ^ swa)];
                vh[1] = Vs[kvb * 64 + (c ^ swb)];
                mma_tf32(o[na], ph, vh);
                mma_tf32(o[na], pl, vh);
            }
        }
        __syncthreads();
    }

    // Epilogue
    float i0 = 1.0f / lrow[0];
    float i1 = 1.0f / lrow[1];
    float* Ob = O + ((size_t)(b * Sq + q0) * Hq) + ho;
#pragma unroll
    for (int na = 0; na < 8; ++na) {
        int col = na * 8 + 2 * tig;
        *(float2*)&Ob[(size_t)R * Hq + col] =
            make_float2(o[na][0] * i0, o[na][1] * i0);
        *(float2*)&Ob[(size_t)R8 * Hq + col] =
            make_float2(o[na][2] * i1, o[na][3] * i1);
    }
}

// ---------------------------------------------------------------------------
// Launch
// ---------------------------------------------------------------------------
extern "C" void kernel_launch(void* const* d_in, const int* in_sizes, int n_in,
                              void* d_out, int out_size) {
    const float* X    = (const float*)d_in[0];
    const float* mask = (const float*)d_in[1];
    const float* cs   = (const float*)d_in[2];
    const float* sn   = (const float*)d_in[3];
    const float* Wq   = (const float*)d_in[4];
    const float* Wk   = (const float*)d_in[5];
    const float* Wv   = (const float*)d_in[6];
    const float* Wo   = (const float*)d_in[7];
    float* out = (float*)d_out;

    float *Qp, *Kp, *Vp, *Ap;
    cudaGetSymbolAddress((void**)&Qp, g_Q);
    cudaGetSymbolAddress((void**)&Kp, g_K);
    cudaGetSymbolAddress((void**)&Vp, g_V);
    cudaGetSymbolAddress((void**)&Ap, g_A);

    const int M = Bq * Sq;                                    // 4096
    const size_t shm_g = (size_t)GSSTR * sizeof(uint32_t);    // 52,224
    const size_t shm_a = 24640u * sizeof(uint32_t);           // 98,560

    static bool attr_set = false;
    if (!attr_set) {
        cudaFuncSetAttribute(sgemm_tf32_nt,
                             cudaFuncAttributeMaxDynamicSharedMemorySize,
                             (int)shm_g);
        cudaFuncSetAttribute(sgemm_tf32_qkv,
                             cudaFuncAttributeMaxDynamicSharedMemorySize,
                             (int)shm_g);
        cudaFuncSetAttribute(attn_mma,
                             cudaFuncAttributeMaxDynamicSharedMemorySize,
                             (int)shm_a);
        attr_set = true;
    }

    sgemm_tf32_qkv<<<dim3(48, M / 128), 256, shm_g>>>(X, Wq, Wk, Wv,
                                                      Qp, Kp, Vp);

    const int PAIRS = Bq * Sq * NHq * (HDq / 2);
    rope_kernel<<<(2 * PAIRS + 255) / 256, 256>>>(Qp, Kp, cs, sn);

    attn_mma<<<dim3(Sq / 128, NHq, Bq), 256, shm_a>>>(Qp, Kp, Vp, mask, Ap);

    sgemm_tf32_nt<<<dim3(Hq / 128, M / 128), 256, shm_g>>>(Ap, Wo, out,
                                                           M, Hq, Hq);
}